// round 7
// baseline (speedup 1.0000x reference)
#include <cuda_runtime.h>

#define BB 8
#define TTOT 100
#define NN 100000
#define MARGIN_F 0.1f
#define THRESH_F 0.5f
#define T_TILE 20
#define NTT (TTOT / T_TILE)
#define NSPLIT 32
#define NTHREADS 128
#define NBLOCKS (NSPLIT * NTT * BB)

// Scratch (device globals; no allocation). Zero-initialized at module load;
// the last block re-zeroes them so every graph replay starts clean.
__device__ int    g_acc[BB * TTOT];   // per-(b,t) max, float bits (>= 0)
__device__ unsigned int g_done;

__device__ __forceinline__ float fast_sqrt(float x) {
    float r;
    asm("sqrt.approx.f32 %0, %1;" : "=f"(r) : "f"(x));
    return r;
}

__global__ void __launch_bounds__(NTHREADS) fused_kernel(
    const float* __restrict__ outputs,
    const float* __restrict__ c2ws,
    const float* __restrict__ ss,
    const float* __restrict__ means,
    const float* __restrict__ scales,
    float* __restrict__ out)
{
    const int b  = blockIdx.z;
    const int tt = blockIdx.y;
    const int s  = blockIdx.x;
    const int tbase = tt * T_TILE;
    const int tid  = threadIdx.x;
    const int lane = tid & 31;
    const int wrp  = tid >> 5;

    __shared__ float4 sh_r[TTOT];
    __shared__ float  sh_lb[3], sh_ub[3];

    // ---- Prologue: retrajs for this b (threads 0..99) ----
    if (tid < TTOT) {
        const float  sb = ss[b];
        const float* o  = outputs + (b * TTOT + tid) * 3;
        const float* M  = c2ws + b * 16;
        float o0 = o[0], o1 = o[1], o2 = o[2];
        float r0 = fmaf(o0, M[0] * sb, fmaf(o1, M[1] * sb, fmaf(o2, M[2]  * sb, M[3])));
        float r1 = fmaf(o0, M[4] * sb, fmaf(o1, M[5] * sb, fmaf(o2, M[6]  * sb, M[7])));
        float r2 = fmaf(o0, M[8] * sb, fmaf(o1, M[9] * sb, fmaf(o2, M[10] * sb, M[11])));
        float rr2 = fmaf(r0, r0, fmaf(r1, r1, r2 * r2));
        sh_r[tid] = make_float4(r0, r1, r2, rr2);
    }
    __syncthreads();

    // ---- Bounds: warp e reduces min/max of dim e over t ----
    if (wrp < 3) {
        float mn = 1e30f, mx = -1e30f;
        for (int t = lane; t < TTOT; t += 32) {
            float4 rr = sh_r[t];
            float v = (wrp == 0) ? rr.x : ((wrp == 1) ? rr.y : rr.z);
            mn = fminf(mn, v);
            mx = fmaxf(mx, v);
        }
        #pragma unroll
        for (int o = 16; o > 0; o >>= 1) {
            mn = fminf(mn, __shfl_xor_sync(0xffffffffu, mn, o));
            mx = fmaxf(mx, __shfl_xor_sync(0xffffffffu, mx, o));
        }
        if (lane == 0) {
            float thres = THRESH_F * ss[0];
            sh_lb[wrp] = mn - thres;
            sh_ub[wrp] = mx + thres;
        }
    }
    __syncthreads();

    const float lb0 = sh_lb[0], lb1 = sh_lb[1], lb2 = sh_lb[2];
    const float ub0 = sh_ub[0], ub1 = sh_ub[1], ub2 = sh_ub[2];

    // ---- Register tile of 20 trajectory points ----
    float rx[T_TILE], ry[T_TILE], rz[T_TILE], C[T_TILE], acc[T_TILE];
    #pragma unroll
    for (int j = 0; j < T_TILE; j++) {
        float4 r = sh_r[tbase + j];
        rx[j] = r.x; ry[j] = r.y; rz[j] = r.z; C[j] = r.w;
        acc[j] = 0.0f;
    }

    // ---- Main loop over this block's point chunk ----
    const int chunk = NN / NSPLIT;               // 3125
    const int n0 = s * chunk;
    const int n1 = (s == NSPLIT - 1) ? NN : (n0 + chunk);

    #pragma unroll 2
    for (int n = n0 + tid; n < n1; n += NTHREADS) {
        float mx_ = means[n * 3 + 0];
        float my_ = means[n * 3 + 1];
        float mz_ = means[n * 3 + 2];
        float s0 = scales[n * 3 + 0];
        float s1 = scales[n * 3 + 1];
        float s2 = scales[n * 3 + 2];
        float rad = fmaxf(s0, fmaxf(s1, s2));
        bool inside = (mx_ >= lb0) & (mx_ <= ub0) &
                      (my_ >= lb1) & (my_ <= ub1) &
                      (mz_ >= lb2) & (mz_ <= ub2);
        float w  = inside ? (rad + MARGIN_F) : -1e30f;
        float px = -2.0f * mx_;
        float py = -2.0f * my_;
        float pz = -2.0f * mz_;
        float m2 = fmaf(mx_, mx_, fmaf(my_, my_, mz_ * mz_));

        #pragma unroll
        for (int j = 0; j < T_TILE; j++) {
            float d2 = C[j] + m2;
            d2 = fmaf(px, rx[j], d2);
            d2 = fmaf(py, ry[j], d2);
            d2 = fmaf(pz, rz[j], d2);
            d2 = fmaxf(d2, 0.0f);
            float v = w - fast_sqrt(d2);
            acc[j] = fmaxf(acc[j], v);
        }
    }

    // ---- Block reduction: warp shfl max, then cross-warp via shared ----
    __shared__ float red[T_TILE][NTHREADS / 32];
    #pragma unroll
    for (int j = 0; j < T_TILE; j++) {
        float v = acc[j];
        #pragma unroll
        for (int o = 16; o > 0; o >>= 1)
            v = fmaxf(v, __shfl_xor_sync(0xffffffffu, v, o));
        if (lane == 0) red[j][wrp] = v;
    }
    __syncthreads();
    if (tid < T_TILE) {
        float v = red[tid][0];
        #pragma unroll
        for (int w = 1; w < NTHREADS / 32; w++)
            v = fmaxf(v, red[tid][w]);
        if (v > 0.0f)
            atomicMax(&g_acc[b * TTOT + tbase + tid], __float_as_int(v));
    }

    // ---- Fused final reduction: last block sums, writes scalar, re-zeroes ----
    __shared__ bool isLast;
    __threadfence();
    __syncthreads();
    if (tid == 0) {
        unsigned int prev = atomicAdd(&g_done, 1u);
        isLast = (prev == (unsigned int)(NBLOCKS - 1));
    }
    __syncthreads();
    if (isLast) {
        __shared__ float sh[NTHREADS];
        float sum = 0.0f;
        for (int i = tid; i < BB * TTOT; i += NTHREADS) {
            sum += __int_as_float(g_acc[i]);
            g_acc[i] = 0;                      // reset for next replay
        }
        sh[tid] = sum;
        __syncthreads();
        for (int o = NTHREADS / 2; o > 0; o >>= 1) {
            if (tid < o) sh[tid] += sh[tid + o];
            __syncthreads();
        }
        if (tid == 0) {
            out[0] = sh[0] / (float)(BB * TTOT);
            g_done = 0;                        // reset for next replay
        }
    }
}

extern "C" void kernel_launch(void* const* d_in, const int* in_sizes, int n_in,
                              void* d_out, int out_size) {
    const float* outputs = (const float*)d_in[0];  // (8,100,3)
    const float* c2ws    = (const float*)d_in[1];  // (8,4,4)
    const float* ss      = (const float*)d_in[2];  // (8,)
    const float* means   = (const float*)d_in[3];  // (100000,3)
    const float* scales  = (const float*)d_in[4];  // (100000,3)
    float* out = (float*)d_out;

    fused_kernel<<<dim3(NSPLIT, NTT, BB), NTHREADS>>>(
        outputs, c2ws, ss, means, scales, out);
}

// round 8
// speedup vs baseline: 1.1209x; 1.1209x over previous
#include <cuda_runtime.h>

#define BB 8
#define TTOT 100
#define NN 100000
#define MARGIN_F 0.1f
#define THRESH_F 0.5f
#define T_TILE 20
#define NTT (TTOT / T_TILE)
#define NSPLIT 64
#define CHUNK 1563                      // ceil(NN / NSPLIT)
#define NTHREADS 128
#define NITEMS (BB * NTT * NSPLIT)      // 2560
#define GRID 592                        // 4 blocks/SM * 148 SMs

// Scratch (device globals; no allocation). Zero at load; last block re-zeroes
// everything so each graph replay starts clean.
__device__ int          g_acc[BB * TTOT];
__device__ unsigned int g_done;
__device__ unsigned int g_work;

__device__ __forceinline__ float fast_sqrt(float x) {
    float r;
    asm("sqrt.approx.f32 %0, %1;" : "=f"(r) : "f"(x));
    return r;
}

__global__ void __launch_bounds__(NTHREADS, 4) fused_kernel(
    const float* __restrict__ outputs,
    const float* __restrict__ c2ws,
    const float* __restrict__ ss,
    const float* __restrict__ means,
    const float* __restrict__ scales,
    float* __restrict__ out)
{
    const int tid  = threadIdx.x;
    const int lane = tid & 31;
    const int wrp  = tid >> 5;

    __shared__ float4 sh_r[TTOT];
    __shared__ float  sh_lb[3], sh_ub[3];
    __shared__ unsigned int sh_item;

    int prev_b = -1;
    float lb0 = 0.f, lb1 = 0.f, lb2 = 0.f, ub0 = 0.f, ub1 = 0.f, ub2 = 0.f;

    for (;;) {
        if (tid == 0) sh_item = atomicAdd(&g_work, 1u);
        __syncthreads();
        unsigned int it = sh_item;
        __syncthreads();                   // protect sh_item before next write
        if (it >= NITEMS) break;

        const int b  = it / (NTT * NSPLIT);
        const int r_ = it - b * (NTT * NSPLIT);
        const int tt = r_ / NSPLIT;
        const int s  = r_ - tt * NSPLIT;
        const int tbase = tt * T_TILE;

        // ---- Prologue (only when b changes): retrajs + bounds ----
        if (b != prev_b) {
            prev_b = b;
            if (tid < TTOT) {
                const float  sb = ss[b];
                const float* o  = outputs + (b * TTOT + tid) * 3;
                const float* M  = c2ws + b * 16;
                float o0 = o[0], o1 = o[1], o2 = o[2];
                float r0 = fmaf(o0, M[0] * sb, fmaf(o1, M[1] * sb, fmaf(o2, M[2]  * sb, M[3])));
                float r1 = fmaf(o0, M[4] * sb, fmaf(o1, M[5] * sb, fmaf(o2, M[6]  * sb, M[7])));
                float r2 = fmaf(o0, M[8] * sb, fmaf(o1, M[9] * sb, fmaf(o2, M[10] * sb, M[11])));
                float rr2 = fmaf(r0, r0, fmaf(r1, r1, r2 * r2));
                sh_r[tid] = make_float4(r0, r1, r2, rr2);
            }
            __syncthreads();
            if (wrp < 3) {
                float mn = 1e30f, mx = -1e30f;
                for (int t = lane; t < TTOT; t += 32) {
                    float4 rr = sh_r[t];
                    float v = (wrp == 0) ? rr.x : ((wrp == 1) ? rr.y : rr.z);
                    mn = fminf(mn, v);
                    mx = fmaxf(mx, v);
                }
                #pragma unroll
                for (int o = 16; o > 0; o >>= 1) {
                    mn = fminf(mn, __shfl_xor_sync(0xffffffffu, mn, o));
                    mx = fmaxf(mx, __shfl_xor_sync(0xffffffffu, mx, o));
                }
                if (lane == 0) {
                    float thres = THRESH_F * ss[0];
                    sh_lb[wrp] = mn - thres;
                    sh_ub[wrp] = mx + thres;
                }
            }
            __syncthreads();
            lb0 = sh_lb[0]; lb1 = sh_lb[1]; lb2 = sh_lb[2];
            ub0 = sh_ub[0]; ub1 = sh_ub[1]; ub2 = sh_ub[2];
        }

        // ---- Register tile of T_TILE trajectory points ----
        float rx[T_TILE], ry[T_TILE], rz[T_TILE], C[T_TILE], acc[T_TILE];
        #pragma unroll
        for (int j = 0; j < T_TILE; j++) {
            float4 rr = sh_r[tbase + j];
            rx[j] = rr.x; ry[j] = rr.y; rz[j] = rr.z; C[j] = rr.w;
            acc[j] = 0.0f;
        }

        // ---- Main loop over this item's point chunk ----
        const int n0 = s * CHUNK;
        const int n1 = (n0 + CHUNK > NN) ? NN : (n0 + CHUNK);

        #pragma unroll 2
        for (int n = n0 + tid; n < n1; n += NTHREADS) {
            float mx_ = means[n * 3 + 0];
            float my_ = means[n * 3 + 1];
            float mz_ = means[n * 3 + 2];
            float s0 = scales[n * 3 + 0];
            float s1 = scales[n * 3 + 1];
            float s2 = scales[n * 3 + 2];
            float rad = fmaxf(s0, fmaxf(s1, s2));
            bool inside = (mx_ >= lb0) & (mx_ <= ub0) &
                          (my_ >= lb1) & (my_ <= ub1) &
                          (mz_ >= lb2) & (mz_ <= ub2);
            float w  = inside ? (rad + MARGIN_F) : -1e30f;
            float px = -2.0f * mx_;
            float py = -2.0f * my_;
            float pz = -2.0f * mz_;
            float m2 = fmaf(mx_, mx_, fmaf(my_, my_, mz_ * mz_));

            #pragma unroll
            for (int j = 0; j < T_TILE; j++) {
                float d2 = C[j] + m2;
                d2 = fmaf(px, rx[j], d2);
                d2 = fmaf(py, ry[j], d2);
                d2 = fmaf(pz, rz[j], d2);
                // d2 < 0 only from rounding at dist≈0; sqrt->NaN, fmaxf drops it
                float v = w - fast_sqrt(d2);
                acc[j] = fmaxf(acc[j], v);
            }
        }

        // ---- Block reduction: warp shfl max, then cross-warp via shared ----
        __shared__ float red[T_TILE][NTHREADS / 32];
        #pragma unroll
        for (int j = 0; j < T_TILE; j++) {
            float v = acc[j];
            #pragma unroll
            for (int o = 16; o > 0; o >>= 1)
                v = fmaxf(v, __shfl_xor_sync(0xffffffffu, v, o));
            if (lane == 0) red[j][wrp] = v;
        }
        __syncthreads();
        if (tid < T_TILE) {
            float v = red[tid][0];
            #pragma unroll
            for (int w = 1; w < NTHREADS / 32; w++)
                v = fmaxf(v, red[tid][w]);
            if (v > 0.0f)
                atomicMax(&g_acc[b * TTOT + tbase + tid], __float_as_int(v));
        }
        __syncthreads();                   // red[] reuse safety on next item
    }

    // ---- Last finishing block: final sum, write scalar, reset state ----
    __shared__ bool isLast;
    __threadfence();
    if (tid == 0) {
        unsigned int prev = atomicAdd(&g_done, 1u);
        isLast = (prev == (unsigned int)(GRID - 1));
    }
    __syncthreads();
    if (isLast) {
        __shared__ float sh[NTHREADS];
        float sum = 0.0f;
        for (int i = tid; i < BB * TTOT; i += NTHREADS) {
            sum += __int_as_float(g_acc[i]);
            g_acc[i] = 0;                  // reset for next replay
        }
        sh[tid] = sum;
        __syncthreads();
        for (int o = NTHREADS / 2; o > 0; o >>= 1) {
            if (tid < o) sh[tid] += sh[tid + o];
            __syncthreads();
        }
        if (tid == 0) {
            out[0] = sh[0] / (float)(BB * TTOT);
            g_work = 0;                    // reset for next replay
            g_done = 0;
        }
    }
}

extern "C" void kernel_launch(void* const* d_in, const int* in_sizes, int n_in,
                              void* d_out, int out_size) {
    const float* outputs = (const float*)d_in[0];  // (8,100,3)
    const float* c2ws    = (const float*)d_in[1];  // (8,4,4)
    const float* ss      = (const float*)d_in[2];  // (8,)
    const float* means   = (const float*)d_in[3];  // (100000,3)
    const float* scales  = (const float*)d_in[4];  // (100000,3)
    float* out = (float*)d_out;

    fused_kernel<<<GRID, NTHREADS>>>(outputs, c2ws, ss, means, scales, out);
}